// round 11
// baseline (speedup 1.0000x reference)
#include <cuda_runtime.h>
#include <cstdint>

// MultiLevelEmbedding: out[b,t,:] = emb_tables[level_ids[b,t], token_ids[b,t], :]
//                                   + level_embed[level_ids[b,t], :]
// B=64, T=1024, L=4, VOCAB=258, D=512 (float32).
//
// R11 = R10 (single-kernel producer/consumer fusion) with the correctness
// fix: consumers read g_fused with ld.global.cg (__ldcg, L2-only, coherent)
// instead of __ldg (LDG.NC, non-coherent -> stale reads of same-kernel
// writes, the R10 rel_err=7.7e-3 failure).
//  - Blocks bid<512 fuse a 258-float4 slice of the 2.1 MB table first,
//    __threadfence + red.release counter.
//  - All blocks do index pre-work, acquire-spin until counter==512 (late
//    blocks pass instantly), then run the pure-gather body pinned at the
//    ~24.5-25.4 us output-write wall (R3/R5/R7).
//  - Exit protocol: last of 4096 blocks resets counters for graph replay.
// Deadlock safety: __launch_bounds__(256,6) -> >=888 resident blocks >= 512
// producers; initial dispatch is bid-ordered.
// Index dtype (int64 vs int32) via per-warp ballot on odd 32-bit words of
// token_ids (values < 258 => odd words all-zero iff int64; P(false) ~ 0).

#define D_VEC       128                 // float4 per row (D=512)
#define VOCAB_SZ    258
#define L_LVL       4
#define N_POS       (64 * 1024)         // B*T rows
#define LVL_VEC     (VOCAB_SZ * D_VEC)  // 33024 float4 per level
#define FUSED_N     (L_LVL * LVL_VEC)   // 132096 float4 = 2.1 MB
#define N_BLOCKS    (N_POS / 16)        // 4096 (2 rows/warp, 8 warps/block)
#define N_FUSE_BLKS 512
#define FUSE_PER_BLK (FUSED_N / N_FUSE_BLKS)   // 258

__device__ float4   g_fused[FUSED_N];
__device__ unsigned g_fuse_done;   // zero-init; reset by exit protocol
__device__ unsigned g_exit_done;

__global__ __launch_bounds__(256, 6)
void mle_kernel(const void* __restrict__ level_ids_raw,
                const void* __restrict__ token_ids_raw,
                const float4* __restrict__ emb_tables,
                const float4* __restrict__ level_embed,
                float4* __restrict__ out) {
    const int bid  = blockIdx.x;
    const int tid  = threadIdx.x;
    const int lane = tid & 31;

    // ---- Phase 1: producer blocks fuse their table slice first ----
    if (bid < N_FUSE_BLKS) {
        const int base = bid * FUSE_PER_BLK;
        #pragma unroll 2
        for (int i = tid; i < FUSE_PER_BLK; i += 256) {
            const int g = base + i;
            const int c = g & (D_VEC - 1);
            const int l = g / LVL_VEC;
            const float4 a = __ldg(emb_tables + g);        // true read-only
            const float4 b = __ldg(level_embed + l * D_VEC + c);
            float4 r;
            r.x = a.x + b.x; r.y = a.y + b.y;
            r.z = a.z + b.z; r.w = a.w + b.w;
            g_fused[g] = r;
        }
        __threadfence();                 // gpu-scope: slice visible
        __syncthreads();
        if (tid == 0) {
            asm volatile("red.release.gpu.global.add.u32 [%0], 1;"
                         :: "l"(&g_fuse_done) : "memory");
        }
    }

    // ---- Phase 2: pre-wait work: dtype detection + index loads ----
    const uint32_t* tr = (const uint32_t*)token_ids_raw;
    const unsigned nz  = __ballot_sync(0xffffffffu, tr[2 * lane + 1] != 0u);
    const bool is64    = (nz == 0u);

    const int warp = (bid * 256 + tid) >> 5;
    const int pos0 = warp * 2;
    const int pos1 = pos0 + 1;

    long long l0, t0, l1, t1;
    if (is64) {
        l0 = ((const long long*)level_ids_raw)[pos0];
        t0 = ((const long long*)token_ids_raw)[pos0];
        l1 = ((const long long*)level_ids_raw)[pos1];
        t1 = ((const long long*)token_ids_raw)[pos1];
    } else {
        l0 = ((const int*)level_ids_raw)[pos0];
        t0 = ((const int*)token_ids_raw)[pos0];
        l1 = ((const int*)level_ids_raw)[pos1];
        t1 = ((const int*)token_ids_raw)[pos1];
    }

    const float4* __restrict__ r0 = g_fused + (l0 * VOCAB_SZ + t0) * D_VEC;
    const float4* __restrict__ r1 = g_fused + (l1 * VOCAB_SZ + t1) * D_VEC;
    float4* __restrict__ o0 = out + (long long)pos0 * D_VEC;
    float4* __restrict__ o1 = out + (long long)pos1 * D_VEC;

    // ---- Phase 3: wait for all fuse slices (acquire; fast path = 1 load) ----
    {
        unsigned v;
        asm volatile("ld.acquire.gpu.global.u32 %0, [%1];"
                     : "=r"(v) : "l"(&g_fuse_done) : "memory");
        while (v < N_FUSE_BLKS) {
            __nanosleep(128);
            asm volatile("ld.acquire.gpu.global.u32 %0, [%1];"
                         : "=r"(v) : "l"(&g_fuse_done) : "memory");
        }
    }

    // ---- Phase 4: pure gather at the write wall (coherent L2 reads) ----
    float4 a0 = __ldcg(r0 + lane);
    float4 a1 = __ldcg(r0 + lane + 32);
    float4 a2 = __ldcg(r0 + lane + 64);
    float4 a3 = __ldcg(r0 + lane + 96);
    float4 b0 = __ldcg(r1 + lane);
    float4 b1 = __ldcg(r1 + lane + 32);
    float4 b2 = __ldcg(r1 + lane + 64);
    float4 b3 = __ldcg(r1 + lane + 96);

    __stcs(o0 + lane,      a0);
    __stcs(o0 + lane + 32, a1);
    __stcs(o0 + lane + 64, a2);
    __stcs(o0 + lane + 96, a3);
    __stcs(o1 + lane,      b0);
    __stcs(o1 + lane + 32, b1);
    __stcs(o1 + lane + 64, b2);
    __stcs(o1 + lane + 96, b3);

    // ---- Phase 5: exit protocol — last block resets replay state ----
    __syncthreads();
    if (tid == 0) {
        const unsigned d = atomicAdd(&g_exit_done, 1);
        if (d == (unsigned)(N_BLOCKS - 1)) {
            atomicExch(&g_fuse_done, 0u);
            atomicExch(&g_exit_done, 0u);
        }
    }
}

extern "C" void kernel_launch(void* const* d_in, const int* in_sizes, int n_in,
                              void* d_out, int out_size) {
    const void*   level_ids  = d_in[0];
    const void*   token_ids  = d_in[1];
    const float4* emb_tables = (const float4*)d_in[2];
    const float4* level_emb  = (const float4*)d_in[3];
    float4*       out        = (float4*)d_out;

    mle_kernel<<<N_BLOCKS, 256>>>(level_ids, token_ids,
                                  emb_tables, level_emb, out);
}

// round 12
// speedup vs baseline: 1.6104x; 1.6104x over previous
#include <cuda_runtime.h>
#include <cstdint>

// MultiLevelEmbedding: out[b,t,:] = emb_tables[level_ids[b,t], token_ids[b,t], :]
//                                   + level_embed[level_ids[b,t], :]
// B=64, T=1024, L=4, VOCAB=258, D=512 (float32).
//
// R12 = R11 (single-kernel producer/consumer fusion, coherent __ldcg reads)
// with the spin-contention fix: only tid==0 of each block polls the done
// counter (sleep-free first check, then 1 us nanosleep backoff); the other
// 255 threads wait at __syncthreads (no memory traffic). R11's all-thread
// ld.acquire.gpu spin (~18 strong loads/cycle on one L2 slice) starved the
// producers and doubled runtime.
//  - Blocks bid<512 fuse a 258-float4 slice of the 2.1 MB table first,
//    __threadfence + red.release counter.
//  - All blocks: index pre-work -> t0 acquire-poll -> __syncthreads ->
//    pure-gather body at the ~24.5-25.4 us output-write wall (R3/R5/R7).
//  - Exit protocol: last of 4096 blocks resets counters for graph replay.
// Deadlock safety: __launch_bounds__(256,6) -> >=888 resident blocks >= 512
// producers; initial dispatch is bid-ordered.
// Index dtype (int64 vs int32) via per-warp ballot on odd 32-bit words of
// token_ids (values < 258 => odd words all-zero iff int64; P(false) ~ 0).

#define D_VEC       128                 // float4 per row (D=512)
#define VOCAB_SZ    258
#define L_LVL       4
#define N_POS       (64 * 1024)         // B*T rows
#define LVL_VEC     (VOCAB_SZ * D_VEC)  // 33024 float4 per level
#define FUSED_N     (L_LVL * LVL_VEC)   // 132096 float4 = 2.1 MB
#define N_BLOCKS    (N_POS / 16)        // 4096 (2 rows/warp, 8 warps/block)
#define N_FUSE_BLKS 512
#define FUSE_PER_BLK (FUSED_N / N_FUSE_BLKS)   // 258

__device__ float4   g_fused[FUSED_N];
__device__ unsigned g_fuse_done;   // zero-init; reset by exit protocol
__device__ unsigned g_exit_done;

__global__ __launch_bounds__(256, 6)
void mle_kernel(const void* __restrict__ level_ids_raw,
                const void* __restrict__ token_ids_raw,
                const float4* __restrict__ emb_tables,
                const float4* __restrict__ level_embed,
                float4* __restrict__ out) {
    const int bid  = blockIdx.x;
    const int tid  = threadIdx.x;
    const int lane = tid & 31;

    // ---- Phase 1: producer blocks fuse their table slice first ----
    if (bid < N_FUSE_BLKS) {
        const int base = bid * FUSE_PER_BLK;
        #pragma unroll 2
        for (int i = tid; i < FUSE_PER_BLK; i += 256) {
            const int g = base + i;
            const int c = g & (D_VEC - 1);
            const int l = g / LVL_VEC;
            const float4 a = __ldg(emb_tables + g);        // true read-only
            const float4 b = __ldg(level_embed + l * D_VEC + c);
            float4 r;
            r.x = a.x + b.x; r.y = a.y + b.y;
            r.z = a.z + b.z; r.w = a.w + b.w;
            g_fused[g] = r;
        }
        __threadfence();                 // gpu-scope: slice visible
        __syncthreads();
        if (tid == 0) {
            asm volatile("red.release.gpu.global.add.u32 [%0], 1;"
                         :: "l"(&g_fuse_done) : "memory");
        }
    }

    // ---- Phase 2: pre-wait work: dtype detection + index loads ----
    const uint32_t* tr = (const uint32_t*)token_ids_raw;
    const unsigned nz  = __ballot_sync(0xffffffffu, tr[2 * lane + 1] != 0u);
    const bool is64    = (nz == 0u);

    const int warp = (bid * 256 + tid) >> 5;
    const int pos0 = warp * 2;
    const int pos1 = pos0 + 1;

    long long l0, t0, l1, t1;
    if (is64) {
        l0 = ((const long long*)level_ids_raw)[pos0];
        t0 = ((const long long*)token_ids_raw)[pos0];
        l1 = ((const long long*)level_ids_raw)[pos1];
        t1 = ((const long long*)token_ids_raw)[pos1];
    } else {
        l0 = ((const int*)level_ids_raw)[pos0];
        t0 = ((const int*)token_ids_raw)[pos0];
        l1 = ((const int*)level_ids_raw)[pos1];
        t1 = ((const int*)token_ids_raw)[pos1];
    }

    const float4* __restrict__ r0 = g_fused + (l0 * VOCAB_SZ + t0) * D_VEC;
    const float4* __restrict__ r1 = g_fused + (l1 * VOCAB_SZ + t1) * D_VEC;
    float4* __restrict__ o0 = out + (long long)pos0 * D_VEC;
    float4* __restrict__ o1 = out + (long long)pos1 * D_VEC;

    // ---- Phase 3: t0-only acquire poll, barrier-broadcast to the block ----
    if (tid == 0) {
        unsigned v;
        asm volatile("ld.acquire.gpu.global.u32 %0, [%1];"
                     : "=r"(v) : "l"(&g_fuse_done) : "memory");
        while (v < N_FUSE_BLKS) {
            __nanosleep(1024);          // ~1 us backoff: <=888 polls/us chip
            asm volatile("ld.acquire.gpu.global.u32 %0, [%1];"
                         : "=r"(v) : "l"(&g_fuse_done) : "memory");
        }
    }
    __syncthreads();                    // chains t0's acquire to all threads

    // ---- Phase 4: pure gather at the write wall (coherent L2 reads) ----
    float4 a0 = __ldcg(r0 + lane);
    float4 a1 = __ldcg(r0 + lane + 32);
    float4 a2 = __ldcg(r0 + lane + 64);
    float4 a3 = __ldcg(r0 + lane + 96);
    float4 b0 = __ldcg(r1 + lane);
    float4 b1 = __ldcg(r1 + lane + 32);
    float4 b2 = __ldcg(r1 + lane + 64);
    float4 b3 = __ldcg(r1 + lane + 96);

    __stcs(o0 + lane,      a0);
    __stcs(o0 + lane + 32, a1);
    __stcs(o0 + lane + 64, a2);
    __stcs(o0 + lane + 96, a3);
    __stcs(o1 + lane,      b0);
    __stcs(o1 + lane + 32, b1);
    __stcs(o1 + lane + 64, b2);
    __stcs(o1 + lane + 96, b3);

    // ---- Phase 5: exit protocol — last block resets replay state ----
    __syncthreads();
    if (tid == 0) {
        const unsigned d = atomicAdd(&g_exit_done, 1);
        if (d == (unsigned)(N_BLOCKS - 1)) {
            atomicExch(&g_fuse_done, 0u);
            atomicExch(&g_exit_done, 0u);
        }
    }
}

extern "C" void kernel_launch(void* const* d_in, const int* in_sizes, int n_in,
                              void* d_out, int out_size) {
    const void*   level_ids  = d_in[0];
    const void*   token_ids  = d_in[1];
    const float4* emb_tables = (const float4*)d_in[2];
    const float4* level_emb  = (const float4*)d_in[3];
    float4*       out        = (float4*)d_out;

    mle_kernel<<<N_BLOCKS, 256>>>(level_ids, token_ids,
                                  emb_tables, level_emb, out);
}

// round 13
// speedup vs baseline: 1.9049x; 1.1829x over previous
#include <cuda_runtime.h>
#include <cstdint>

// MultiLevelEmbedding: out[b,t,:] = emb_tables[level_ids[b,t], token_ids[b,t], :]
//                                   + level_embed[level_ids[b,t], :]
// B=64, T=1024, L=4, VOCAB=258, D=512 (float32).
//
// R13: single kernel, chunk-split warps. Each warp owns a fixed 128-byte
// column chunk (chunk = warp & 3) of 8 consecutive rows; 4 warps jointly
// cover each row. A warp therefore needs only 4 level_embed float4 in
// registers (one per level, 16 regs) to serve ANY row -> in-register add
// with HIGH occupancy (R8 died at 116 regs / 22.7% occ). Per row-chunk the
// data path is exactly 1 LDG.128 + 1 STG.128 = same wavefront count as the
// pure gather pinned at the ~24.5 us write wall (R3/R5/R7). Level select is
// a warp-uniform FSEL chain (fma-pipe, far from cap). No prologue, no sync.
// Index dtype (int64 vs int32) via per-warp ballot on odd 32-bit words of
// token_ids (values < 258 => odd words all-zero iff int64; P(false) ~ 0).

#define D_VEC     128                 // float4 per row (D=512)
#define VOCAB_SZ  258
#define N_POS     (64 * 1024)         // B*T rows
#define ROWS_PW   8                   // rows per warp (per chunk)
// 4 chunk-warps per row-group: warps = 4 * N_POS / ROWS_PW = 32768
// blocks  = 32768 / 8 = 4096

#define SEL_ADD(dst, A, L)                                             \
    do {                                                               \
        float4 _b;                                                     \
        _b.x = (L)==0 ? b0.x : (L)==1 ? b1.x : (L)==2 ? b2.x : b3.x;   \
        _b.y = (L)==0 ? b0.y : (L)==1 ? b1.y : (L)==2 ? b2.y : b3.y;   \
        _b.z = (L)==0 ? b0.z : (L)==1 ? b1.z : (L)==2 ? b2.z : b3.z;   \
        _b.w = (L)==0 ? b0.w : (L)==1 ? b1.w : (L)==2 ? b2.w : b3.w;   \
        (dst).x = (A).x + _b.x; (dst).y = (A).y + _b.y;                \
        (dst).z = (A).z + _b.z; (dst).w = (A).w + _b.w;                \
    } while (0)

__global__ __launch_bounds__(256)
void mle_kernel(const void* __restrict__ level_ids_raw,
                const void* __restrict__ token_ids_raw,
                const float4* __restrict__ emb_tables,
                const float4* __restrict__ level_embed,
                float4* __restrict__ out) {
    const int lane  = threadIdx.x & 31;
    const int warp  = (blockIdx.x * 256 + threadIdx.x) >> 5;  // 0..32767
    const int chunk = warp & 3;                // which 32-float4 chunk
    const int rbase = (warp >> 2) * ROWS_PW;   // first row of this group
    const int cofs  = chunk * 32 + lane;       // column (float4 units)

    // ---- dtype detection (1 LDG + ballot, warp-uniform) ----
    const uint32_t* tr = (const uint32_t*)token_ids_raw;
    const unsigned nz  = __ballot_sync(0xffffffffu, tr[2 * lane + 1] != 0u);
    const bool is64    = (nz == 0u);

    // ---- this chunk's level_embed values for all 4 levels (16 regs) ----
    const float4 b0 = __ldg(level_embed + 0 * D_VEC + cofs);
    const float4 b1 = __ldg(level_embed + 1 * D_VEC + cofs);
    const float4 b2 = __ldg(level_embed + 2 * D_VEC + cofs);
    const float4 b3 = __ldg(level_embed + 3 * D_VEC + cofs);

    const long long* li64 = (const long long*)level_ids_raw;
    const long long* ti64 = (const long long*)token_ids_raw;
    const int*       li32 = (const int*)level_ids_raw;
    const int*       ti32 = (const int*)token_ids_raw;

    #pragma unroll
    for (int r = 0; r < ROWS_PW; r += 4) {
        const int p0 = rbase + r, p1 = p0 + 1, p2 = p0 + 2, p3 = p0 + 3;

        // warp-uniform index loads (broadcast), 8 independent small LDGs
        int l0, t0, l1, t1, l2, t2, l3, t3;
        if (is64) {
            l0 = (int)li64[p0]; t0 = (int)ti64[p0];
            l1 = (int)li64[p1]; t1 = (int)ti64[p1];
            l2 = (int)li64[p2]; t2 = (int)ti64[p2];
            l3 = (int)li64[p3]; t3 = (int)ti64[p3];
        } else {
            l0 = li32[p0]; t0 = ti32[p0];
            l1 = li32[p1]; t1 = ti32[p1];
            l2 = li32[p2]; t2 = ti32[p2];
            l3 = li32[p3]; t3 = ti32[p3];
        }

        // 4 independent table loads in flight (128B coalesced each)
        const float4 a0 = __ldg(emb_tables + (l0 * VOCAB_SZ + t0) * D_VEC + cofs);
        const float4 a1 = __ldg(emb_tables + (l1 * VOCAB_SZ + t1) * D_VEC + cofs);
        const float4 a2 = __ldg(emb_tables + (l2 * VOCAB_SZ + t2) * D_VEC + cofs);
        const float4 a3 = __ldg(emb_tables + (l3 * VOCAB_SZ + t3) * D_VEC + cofs);

        float4 r0, r1, r2, r3;
        SEL_ADD(r0, a0, l0);
        SEL_ADD(r1, a1, l1);
        SEL_ADD(r2, a2, l2);
        SEL_ADD(r3, a3, l3);

        __stcs(out + (long long)p0 * D_VEC + cofs, r0);
        __stcs(out + (long long)p1 * D_VEC + cofs, r1);
        __stcs(out + (long long)p2 * D_VEC + cofs, r2);
        __stcs(out + (long long)p3 * D_VEC + cofs, r3);
    }
}

extern "C" void kernel_launch(void* const* d_in, const int* in_sizes, int n_in,
                              void* d_out, int out_size) {
    const void*   level_ids  = d_in[0];
    const void*   token_ids  = d_in[1];
    const float4* emb_tables = (const float4*)d_in[2];
    const float4* level_emb  = (const float4*)d_in[3];
    float4*       out        = (float4*)d_out;

    // 32768 warps (4 chunk-warps x 8192 row-groups) / 8 warps per block
    mle_kernel<<<4096, 256>>>(level_ids, token_ids,
                              emb_tables, level_emb, out);
}